// round 12
// baseline (speedup 1.0000x reference)
#include <cuda_runtime.h>
#include <cuda_fp16.h>

#define NN 100000
#define EE 1600000
#define IN_F 128
#define OUT_F 64
#define HH 8
#define BKT 96   // slots per node; P(Poisson(16) >= 96) ~ 1e-40

// ---------------------------------------------------------------------------
// Device-global scratch (no allocations allowed; zero-initialized at load)
// ---------------------------------------------------------------------------
__device__ __half g_qh[NN * OUT_F];    // q fp16
__device__ __half g_kh[NN * OUT_F];    // k fp16
__device__ float  g_vf[NN * OUT_F];    // v fp32 (consumed directly by f32x2 FMA)

__device__ uint2 g_wf[192 * 8 * 4];    // W fp16, HMMA-B fragment order
__device__ float g_bias[192];           // bq|bk|bv concatenated

__device__ int g_cnt[NN];               // per-src cursor (reset by agg tail)
__device__ int g_bkt[NN * BKT];         // dst indices bucketed by src

// packed fp32x2 helpers
#define PACK2(out, lo, hi) \
    asm("mov.b64 %0, {%1, %2};" : "=l"(out) : "f"(lo), "f"(hi))
#define FMA2(d, a, b, c) \
    asm("fma.rn.f32x2 %0, %1, %2, %3;" : "=l"(d) : "l"(a), "l"(b), "l"(c))
#define UNPACK2(lo, hi, in) \
    asm("mov.b64 {%0, %1}, %2;" : "=f"(lo), "=f"(hi) : "l"(in))

// ---------------------------------------------------------------------------
// K0: pack W into HMMA fragment order + biases (tiny).
// ---------------------------------------------------------------------------
__global__ __launch_bounds__(256) void init_kernel(
    const float* __restrict__ Wq, const float* __restrict__ bq,
    const float* __restrict__ Wk, const float* __restrict__ bk,
    const float* __restrict__ Wv, const float* __restrict__ bv)
{
    int idx = blockIdx.x * blockDim.x + threadIdx.x;   // < 6144
    {
        int j  = idx & 3;
        int kb = (idx >> 2) & 7;
        int n  = idx >> 5;
        const float* Wr = (n < 64) ? (Wq + n * IN_F)
                        : (n < 128) ? (Wk + (n - 64) * IN_F)
                                    : (Wv + (n - 128) * IN_F);
        int k = kb * 16 + 2 * j;
        __half2 lo = __floats2half2_rn(Wr[k],     Wr[k + 1]);
        __half2 hi = __floats2half2_rn(Wr[k + 8], Wr[k + 9]);
        uint2 pk;
        pk.x = *reinterpret_cast<unsigned*>(&lo);
        pk.y = *reinterpret_cast<unsigned*>(&hi);
        g_wf[idx] = pk;
    }
    if (idx < 192) {
        g_bias[idx] = (idx < 64) ? bq[idx] : (idx < 128) ? bk[idx - 64] : bv[idx - 128];
    }
}

// ---------------------------------------------------------------------------
// K1: merged GEMM + scatter, interleaved by bid parity (even = GEMM tile,
// odd = scatter chunk of 1024 edges via int4 loads).
// ---------------------------------------------------------------------------
#define XS_LDH 136
#define GEMM_B ((NN + 63) / 64)            // 1563
#define WORK_G (GEMM_B * 2)                // 3126

__global__ __launch_bounds__(256) void work_kernel(
    const float* __restrict__ x, const int* __restrict__ edge)
{
    __shared__ __half Xs[64][XS_LDH];
    const int tid = threadIdx.x;
    const unsigned bid = blockIdx.x;

    if (bid & 1u) {
        // ---------------- scatter: 4 edges per thread (int4) ----------------
        int e = (int)((bid >> 1) * 1024u) + tid * 4;
        if (e + 3 < EE) {
            int4 ss = *reinterpret_cast<const int4*>(&edge[e]);
            int4 dd = *reinterpret_cast<const int4*>(&edge[EE + e]);
            int p;
            p = atomicAdd(&g_cnt[ss.x], 1); if (p < BKT) g_bkt[ss.x * BKT + p] = dd.x;
            p = atomicAdd(&g_cnt[ss.y], 1); if (p < BKT) g_bkt[ss.y * BKT + p] = dd.y;
            p = atomicAdd(&g_cnt[ss.z], 1); if (p < BKT) g_bkt[ss.z * BKT + p] = dd.z;
            p = atomicAdd(&g_cnt[ss.w], 1); if (p < BKT) g_bkt[ss.w * BKT + p] = dd.w;
        } else {
            for (int q = e; q < EE; q++) {
                int s = edge[q], d = edge[EE + q];
                int p = atomicAdd(&g_cnt[s], 1);
                if (p < BKT) g_bkt[s * BKT + p] = d;
            }
        }
        return;
    }

    // ---------------- GEMM ----------------
    const int w = tid >> 5, l = tid & 31;
    const int row0 = (int)(bid >> 1) * 64;

    const float4* x4 = reinterpret_cast<const float4*>(x);
#pragma unroll
    for (int i = 0; i < 8; i++) {
        int idx = tid + 256 * i;
        int r = idx >> 5, c4 = idx & 31;
        int row = row0 + r;
        if (row >= NN) row = NN - 1;
        float4 v = x4[(size_t)row * 32 + c4];
        __half2 h0 = __floats2half2_rn(v.x, v.y);
        __half2 h1 = __floats2half2_rn(v.z, v.w);
        uint2 pk;
        pk.x = *reinterpret_cast<unsigned*>(&h0);
        pk.y = *reinterpret_cast<unsigned*>(&h1);
        *reinterpret_cast<uint2*>(&Xs[r][c4 * 4]) = pk;
    }
    __syncthreads();

    const int wm = w & 3;
    const int nh = w >> 2;
    const int m0 = wm * 16;
    const int g = l >> 2, j = l & 3;

    float c[12][4];
#pragma unroll
    for (int t = 0; t < 12; t++)
#pragma unroll
        for (int p = 0; p < 4; p++) c[t][p] = 0.f;

    const int sel = l >> 3;
    const int a_row = m0 + ((sel & 1) << 3) + (l & 7);
    const int a_col = (sel >> 1) << 3;

#pragma unroll
    for (int kb = 0; kb < 8; kb++) {
        unsigned a0, a1, a2, a3;
        unsigned sa = (unsigned)__cvta_generic_to_shared(&Xs[a_row][kb * 16 + a_col]);
        asm volatile("ldmatrix.sync.aligned.m8n8.x4.shared.b16 {%0,%1,%2,%3}, [%4];"
                     : "=r"(a0), "=r"(a1), "=r"(a2), "=r"(a3) : "r"(sa));

        uint2 bfr[12];
#pragma unroll
        for (int t = 0; t < 12; t++) {
            int n = nh * 96 + t * 8 + g;
            bfr[t] = g_wf[(n * 8 + kb) * 4 + j];
        }
#pragma unroll
        for (int t = 0; t < 12; t++) {
            asm volatile(
                "mma.sync.aligned.m16n8k16.row.col.f32.f16.f16.f32 "
                "{%0,%1,%2,%3}, {%4,%5,%6,%7}, {%8,%9}, {%0,%1,%2,%3};"
                : "+f"(c[t][0]), "+f"(c[t][1]), "+f"(c[t][2]), "+f"(c[t][3])
                : "r"(a0), "r"(a1), "r"(a2), "r"(a3), "r"(bfr[t].x), "r"(bfr[t].y));
        }
    }

    // epilogue: q,k fp16; v fp32
    const int r0g = row0 + m0 + g;
    const int r1g = r0g + 8;
#pragma unroll
    for (int t = 0; t < 12; t++) {
        int n = nh * 96 + t * 8 + 2 * j;
        float2 bb = *reinterpret_cast<const float2*>(&g_bias[n]);
        int m = n >> 6, col = n & 63;
        if (m < 2) {
            __half2 h0 = __floats2half2_rn(c[t][0] + bb.x, c[t][1] + bb.y);
            __half2 h1 = __floats2half2_rn(c[t][2] + bb.x, c[t][3] + bb.y);
            __half* base = (m == 0) ? g_qh : g_kh;
            if (r0g < NN) *reinterpret_cast<__half2*>(&base[(size_t)r0g * 64 + col]) = h0;
            if (r1g < NN) *reinterpret_cast<__half2*>(&base[(size_t)r1g * 64 + col]) = h1;
        } else {
            float2 f0 = make_float2(c[t][0] + bb.x, c[t][1] + bb.y);
            float2 f1 = make_float2(c[t][2] + bb.x, c[t][3] + bb.y);
            if (r0g < NN) *reinterpret_cast<float2*>(&g_vf[(size_t)r0g * 64 + col]) = f0;
            if (r1g < NN) *reinterpret_cast<float2*>(&g_vf[(size_t)r1g * 64 + col]) = f1;
        }
    }
}

// ---------------------------------------------------------------------------
// K2: aggregation.  Warp = 4 nodes; lane = (node_local, head); each lane owns
// the full (node, head) accumulator.  k fp16 (1 LDG.128) + v fp32 (2 LDG.128,
// consumed directly by f32x2 FMA — no conversions, no packs).
// ---------------------------------------------------------------------------
__device__ __forceinline__ void agg_edge(
    int dst, int h, const __half2* qp,
    float& den,
    unsigned long long& acc0, unsigned long long& acc1,
    unsigned long long& acc2, unsigned long long& acc3)
{
    uint4 kv = *reinterpret_cast<const uint4*>(&g_kh[(size_t)dst * 64 + h * 8]);
    const ulonglong2* vp = reinterpret_cast<const ulonglong2*>(&g_vf[(size_t)dst * 64 + h * 8]);
    ulonglong2 va = vp[0];   // v[0..3] as two f32x2 pairs
    ulonglong2 vb = vp[1];   // v[4..7]

    const __half2* k2 = reinterpret_cast<const __half2*>(&kv);
    __half2 pr = __hmul2(qp[0], k2[0]);
    pr = __hfma2(qp[1], k2[1], pr);
    pr = __hfma2(qp[2], k2[2], pr);
    pr = __hfma2(qp[3], k2[3], pr);
    float s = __low2float(pr) + __high2float(pr);
    float ex;
    asm("ex2.approx.f32 %0, %1;" : "=f"(ex) : "f"(s * 0.5101127652f));  // exp(s/sqrt(8))
    den += ex;

    unsigned long long ex2r;
    PACK2(ex2r, ex, ex);
    FMA2(acc0, ex2r, va.x, acc0);
    FMA2(acc1, ex2r, va.y, acc1);
    FMA2(acc2, ex2r, vb.x, acc2);
    FMA2(acc3, ex2r, vb.y, acc3);
}

__global__ __launch_bounds__(256) void agg_kernel(float* __restrict__ out)
{
    const int gw = (blockIdx.x * 256 + threadIdx.x) >> 5;
    const int lane = threadIdx.x & 31;
    const int node = gw * 4 + (lane >> 3);   // exact: 3125*8*4 = 100000
    const int h = lane & 7;
    if (node >= NN) return;

    uint4 qv = *reinterpret_cast<const uint4*>(&g_qh[(size_t)node * 64 + h * 8]);
    const __half2* qp = reinterpret_cast<const __half2*>(&qv);

    int cnt = g_cnt[node];
    if (cnt > BKT) cnt = BKT;
    const int* bp = &g_bkt[node * BKT];

    float den = 0.f;
    unsigned long long acc0, acc1, acc2, acc3;
    PACK2(acc0, 0.f, 0.f);  PACK2(acc1, 0.f, 0.f);
    PACK2(acc2, 0.f, 0.f);  PACK2(acc3, 0.f, 0.f);

    const int full = cnt & ~3;
    for (int t4 = 0; t4 < full; t4 += 4) {
        int4 dd = *reinterpret_cast<const int4*>(&bp[t4]);
        agg_edge(dd.x, h, qp, den, acc0, acc1, acc2, acc3);
        agg_edge(dd.y, h, qp, den, acc0, acc1, acc2, acc3);
        agg_edge(dd.z, h, qp, den, acc0, acc1, acc2, acc3);
        agg_edge(dd.w, h, qp, den, acc0, acc1, acc2, acc3);
    }
    for (int t = full; t < cnt; t++)
        agg_edge(bp[t], h, qp, den, acc0, acc1, acc2, acc3);

    float inv = 1.f / (den + 1e-16f);
    float o[8];
    UNPACK2(o[0], o[1], acc0);  UNPACK2(o[2], o[3], acc1);
    UNPACK2(o[4], o[5], acc2);  UNPACK2(o[6], o[7], acc3);

    float4 o0 = make_float4(o[0] * inv, o[1] * inv, o[2] * inv, o[3] * inv);
    float4 o1 = make_float4(o[4] * inv, o[5] * inv, o[6] * inv, o[7] * inv);
    float4* op = reinterpret_cast<float4*>(&out[(size_t)node * 64 + h * 8]);
    op[0] = o0;
    op[1] = o1;

    if (h == 0) g_cnt[node] = 0;   // restore invariant for next replay
}

extern "C" void kernel_launch(void* const* d_in, const int* in_sizes, int n_in,
                              void* d_out, int out_size)
{
    const float* x    = (const float*)d_in[0];
    const int*   edge = (const int*)d_in[1];
    const float* Wq   = (const float*)d_in[2];
    const float* bq   = (const float*)d_in[3];
    const float* Wk   = (const float*)d_in[4];
    const float* bk   = (const float*)d_in[5];
    const float* Wv   = (const float*)d_in[6];
    const float* bv   = (const float*)d_in[7];
    float* out = (float*)d_out;

    init_kernel<<<24, 256>>>(Wq, bq, Wk, bk, Wv, bv);
    work_kernel<<<WORK_G, 256>>>(x, edge);
    agg_kernel<<<NN / 32, 256>>>(out);   // 3125 blocks = 8 warps x 4 nodes
}

// round 13
// speedup vs baseline: 1.0925x; 1.0925x over previous
#include <cuda_runtime.h>
#include <cuda_fp16.h>

#define NN 100000
#define EE 1600000
#define IN_F 128
#define OUT_F 64
#define HH 8
#define BKT 96   // slots per node; P(Poisson(16) >= 96) ~ 1e-40

// ---------------------------------------------------------------------------
// Device-global scratch (no allocations allowed; zero-initialized at load)
// ---------------------------------------------------------------------------
__device__ __half g_qh[NN * OUT_F];
__device__ __half g_kvh[NN * 128];     // per node: [0:64)=k, [64:128)=v fp16

__device__ uint2 g_wf[192 * 8 * 4];    // W fp16, HMMA-B fragment order
__device__ float g_bias[192];           // bq|bk|bv concatenated

__device__ int g_cnt[NN];               // per-src cursor (reset by agg tail)
__device__ int g_bkt[NN * BKT];         // dst indices bucketed by src

// packed fp32x2 helpers
#define PACK2(out, lo, hi) \
    asm("mov.b64 %0, {%1, %2};" : "=l"(out) : "f"(lo), "f"(hi))
#define FMA2(d, a, b, c) \
    asm("fma.rn.f32x2 %0, %1, %2, %3;" : "=l"(d) : "l"(a), "l"(b), "l"(c))
#define ADD2(d, a, b) \
    asm("add.rn.f32x2 %0, %1, %2;" : "=l"(d) : "l"(a), "l"(b))
#define UNPACK2(lo, hi, in) \
    asm("mov.b64 {%0, %1}, %2;" : "=f"(lo), "=f"(hi) : "l"(in))

// ---------------------------------------------------------------------------
// K0: pack W into HMMA fragment order + biases (tiny).
// ---------------------------------------------------------------------------
__global__ __launch_bounds__(256) void init_kernel(
    const float* __restrict__ Wq, const float* __restrict__ bq,
    const float* __restrict__ Wk, const float* __restrict__ bk,
    const float* __restrict__ Wv, const float* __restrict__ bv)
{
    int idx = blockIdx.x * blockDim.x + threadIdx.x;   // < 6144
    {
        int j  = idx & 3;
        int kb = (idx >> 2) & 7;
        int n  = idx >> 5;
        const float* Wr = (n < 64) ? (Wq + n * IN_F)
                        : (n < 128) ? (Wk + (n - 64) * IN_F)
                                    : (Wv + (n - 128) * IN_F);
        int k = kb * 16 + 2 * j;
        __half2 lo = __floats2half2_rn(Wr[k],     Wr[k + 1]);
        __half2 hi = __floats2half2_rn(Wr[k + 8], Wr[k + 9]);
        uint2 pk;
        pk.x = *reinterpret_cast<unsigned*>(&lo);
        pk.y = *reinterpret_cast<unsigned*>(&hi);
        g_wf[idx] = pk;
    }
    if (idx < 192) {
        g_bias[idx] = (idx < 64) ? bq[idx] : (idx < 128) ? bk[idx - 64] : bv[idx - 128];
    }
}

// ---------------------------------------------------------------------------
// K1: merged GEMM + scatter, roles interleaved by bid % 3 (1 GEMM : 2 scatter)
// so both kinds run concurrently on every SM.
// ---------------------------------------------------------------------------
#define XS_LDH 136
#define GEMM_B ((NN + 63) / 64)            // 1563
#define SCAT_B (EE / (256 * 2))            // 3125 exact
#define WORK_G (GEMM_B * 3)                // 4689

__global__ __launch_bounds__(256) void work_kernel(
    const float* __restrict__ x, const int* __restrict__ edge)
{
    __shared__ __half Xs[64][XS_LDH];
    const int tid = threadIdx.x;
    const unsigned bid = blockIdx.x;

    if (bid % 3u != 0u) {
        // ---------------- scatter: 2 edges per thread ----------------
        int sidx = (int)(bid - bid / 3u - 1u);     // 0..3125
        if (sidx >= SCAT_B) return;
        int e = (sidx * 256 + tid) * 2;
        int2 ss = *reinterpret_cast<const int2*>(&edge[e]);
        int2 dd = *reinterpret_cast<const int2*>(&edge[EE + e]);
        int p0 = atomicAdd(&g_cnt[ss.x], 1);
        if (p0 < BKT) g_bkt[ss.x * BKT + p0] = dd.x;
        int p1 = atomicAdd(&g_cnt[ss.y], 1);
        if (p1 < BKT) g_bkt[ss.y * BKT + p1] = dd.y;
        return;
    }

    // ---------------- GEMM ----------------
    const int w = tid >> 5, l = tid & 31;
    const int row0 = (int)(bid / 3u) * 64;

    const float4* x4 = reinterpret_cast<const float4*>(x);
#pragma unroll
    for (int i = 0; i < 8; i++) {
        int idx = tid + 256 * i;
        int r = idx >> 5, c4 = idx & 31;
        int row = row0 + r;
        if (row >= NN) row = NN - 1;
        float4 v = x4[(size_t)row * 32 + c4];
        __half2 h0 = __floats2half2_rn(v.x, v.y);
        __half2 h1 = __floats2half2_rn(v.z, v.w);
        uint2 pk;
        pk.x = *reinterpret_cast<unsigned*>(&h0);
        pk.y = *reinterpret_cast<unsigned*>(&h1);
        *reinterpret_cast<uint2*>(&Xs[r][c4 * 4]) = pk;
    }
    __syncthreads();

    const int wm = w & 3;
    const int nh = w >> 2;
    const int m0 = wm * 16;
    const int g = l >> 2, j = l & 3;

    float c[12][4];
#pragma unroll
    for (int t = 0; t < 12; t++)
#pragma unroll
        for (int p = 0; p < 4; p++) c[t][p] = 0.f;

    const int sel = l >> 3;
    const int a_row = m0 + ((sel & 1) << 3) + (l & 7);
    const int a_col = (sel >> 1) << 3;

#pragma unroll
    for (int kb = 0; kb < 8; kb++) {
        unsigned a0, a1, a2, a3;
        unsigned sa = (unsigned)__cvta_generic_to_shared(&Xs[a_row][kb * 16 + a_col]);
        asm volatile("ldmatrix.sync.aligned.m8n8.x4.shared.b16 {%0,%1,%2,%3}, [%4];"
                     : "=r"(a0), "=r"(a1), "=r"(a2), "=r"(a3) : "r"(sa));

        uint2 bfr[12];
#pragma unroll
        for (int t = 0; t < 12; t++) {
            int n = nh * 96 + t * 8 + g;
            bfr[t] = g_wf[(n * 8 + kb) * 4 + j];
        }
#pragma unroll
        for (int t = 0; t < 12; t++) {
            asm volatile(
                "mma.sync.aligned.m16n8k16.row.col.f32.f16.f16.f32 "
                "{%0,%1,%2,%3}, {%4,%5,%6,%7}, {%8,%9}, {%0,%1,%2,%3};"
                : "+f"(c[t][0]), "+f"(c[t][1]), "+f"(c[t][2]), "+f"(c[t][3])
                : "r"(a0), "r"(a1), "r"(a2), "r"(a3), "r"(bfr[t].x), "r"(bfr[t].y));
        }
    }

    // epilogue: q -> g_qh; k,v interleaved -> g_kvh
    const int r0g = row0 + m0 + g;
    const int r1g = r0g + 8;
#pragma unroll
    for (int t = 0; t < 12; t++) {
        int n = nh * 96 + t * 8 + 2 * j;
        float2 bb = *reinterpret_cast<const float2*>(&g_bias[n]);
        int m = n >> 6, col = n & 63;
        __half2 h0 = __floats2half2_rn(c[t][0] + bb.x, c[t][1] + bb.y);
        __half2 h1 = __floats2half2_rn(c[t][2] + bb.x, c[t][3] + bb.y);
        if (m == 0) {
            if (r0g < NN) *reinterpret_cast<__half2*>(&g_qh[(size_t)r0g * 64 + col]) = h0;
            if (r1g < NN) *reinterpret_cast<__half2*>(&g_qh[(size_t)r1g * 64 + col]) = h1;
        } else {
            int ofs = (m == 1) ? col : (64 + col);
            if (r0g < NN) *reinterpret_cast<__half2*>(&g_kvh[(size_t)r0g * 128 + ofs]) = h0;
            if (r1g < NN) *reinterpret_cast<__half2*>(&g_kvh[(size_t)r1g * 128 + ofs]) = h1;
        }
    }
}

// ---------------------------------------------------------------------------
// K2: aggregation.  Warp = 4 nodes; lane = (node_local, head); each lane owns
// the full (node, head) accumulator.  Per int4 quad: ex*v accumulated in
// __half2 (HFMA2), flushed ONCE to fp32x2 accumulators — same bytes as R11,
// ~10 fewer instructions per edge.  den stays fp32; remainder edges use the
// fp32 path.
// ---------------------------------------------------------------------------
__device__ __forceinline__ float edge_score(int dst, int h, const __half2* qp,
                                            uint4& vv_out)
{
    const uint4* kvp = reinterpret_cast<const uint4*>(&g_kvh[(size_t)dst * 128]);
    uint4 kv = kvp[h];        // k row (8 halves)
    vv_out   = kvp[8 + h];    // v row (+128B immediate)
    const __half2* k2 = reinterpret_cast<const __half2*>(&kv);
    __half2 pr = __hmul2(qp[0], k2[0]);
    pr = __hfma2(qp[1], k2[1], pr);
    pr = __hfma2(qp[2], k2[2], pr);
    pr = __hfma2(qp[3], k2[3], pr);
    float s = __low2float(pr) + __high2float(pr);
    float ex;
    asm("ex2.approx.f32 %0, %1;" : "=f"(ex) : "f"(s * 0.5101127652f));  // exp(s/sqrt(8))
    return ex;
}

// fp32 path for remainder edges
__device__ __forceinline__ void agg_edge_f32(
    int dst, int h, const __half2* qp, float& den,
    unsigned long long& acc0, unsigned long long& acc1,
    unsigned long long& acc2, unsigned long long& acc3)
{
    uint4 vv;
    float ex = edge_score(dst, h, qp, vv);
    den += ex;
    unsigned long long ex2r;
    PACK2(ex2r, ex, ex);
    const __half2* v2 = reinterpret_cast<const __half2*>(&vv);
    float2 f0 = __half22float2(v2[0]);
    float2 f1 = __half22float2(v2[1]);
    float2 f2 = __half22float2(v2[2]);
    float2 f3 = __half22float2(v2[3]);
    unsigned long long vp0, vp1, vp2, vp3;
    PACK2(vp0, f0.x, f0.y);  PACK2(vp1, f1.x, f1.y);
    PACK2(vp2, f2.x, f2.y);  PACK2(vp3, f3.x, f3.y);
    FMA2(acc0, ex2r, vp0, acc0);
    FMA2(acc1, ex2r, vp1, acc1);
    FMA2(acc2, ex2r, vp2, acc2);
    FMA2(acc3, ex2r, vp3, acc3);
}

__global__ __launch_bounds__(256) void agg_kernel(float* __restrict__ out)
{
    const int gw = (blockIdx.x * 256 + threadIdx.x) >> 5;
    const int lane = threadIdx.x & 31;
    const int node = gw * 4 + (lane >> 3);   // exact: 3125*8*4 = 100000
    const int h = lane & 7;
    if (node >= NN) return;

    uint4 qv = *reinterpret_cast<const uint4*>(&g_qh[(size_t)node * 64 + h * 8]);
    const __half2* qp = reinterpret_cast<const __half2*>(&qv);

    int cnt = g_cnt[node];
    if (cnt > BKT) cnt = BKT;
    const int* bp = &g_bkt[node * BKT];

    float den = 0.f;
    unsigned long long acc0, acc1, acc2, acc3;
    PACK2(acc0, 0.f, 0.f);  PACK2(acc1, 0.f, 0.f);
    PACK2(acc2, 0.f, 0.f);  PACK2(acc3, 0.f, 0.f);

    const int full = cnt & ~3;
    for (int t4 = 0; t4 < full; t4 += 4) {
        int4 dd = *reinterpret_cast<const int4*>(&bp[t4]);
        int dts[4] = {dd.x, dd.y, dd.z, dd.w};

        __half2 va0, va1, va2, va3;   // quad-local fp16 accumulators
#pragma unroll
        for (int u = 0; u < 4; u++) {
            uint4 vv;
            float ex = edge_score(dts[u], h, qp, vv);
            den += ex;
            __half2 exh = __float2half2_rn(ex);
            const __half2* v2 = reinterpret_cast<const __half2*>(&vv);
            if (u == 0) {
                va0 = __hmul2(exh, v2[0]);
                va1 = __hmul2(exh, v2[1]);
                va2 = __hmul2(exh, v2[2]);
                va3 = __hmul2(exh, v2[3]);
            } else {
                va0 = __hfma2(exh, v2[0], va0);
                va1 = __hfma2(exh, v2[1], va1);
                va2 = __hfma2(exh, v2[2], va2);
                va3 = __hfma2(exh, v2[3], va3);
            }
        }
        // flush quad partials to fp32x2 accumulators
        float2 f0 = __half22float2(va0);
        float2 f1 = __half22float2(va1);
        float2 f2 = __half22float2(va2);
        float2 f3 = __half22float2(va3);
        unsigned long long p0, p1, p2, p3;
        PACK2(p0, f0.x, f0.y);  PACK2(p1, f1.x, f1.y);
        PACK2(p2, f2.x, f2.y);  PACK2(p3, f3.x, f3.y);
        ADD2(acc0, acc0, p0);
        ADD2(acc1, acc1, p1);
        ADD2(acc2, acc2, p2);
        ADD2(acc3, acc3, p3);
    }
    for (int t = full; t < cnt; t++)
        agg_edge_f32(bp[t], h, qp, den, acc0, acc1, acc2, acc3);

    float inv = 1.f / (den + 1e-16f);
    float o[8];
    UNPACK2(o[0], o[1], acc0);  UNPACK2(o[2], o[3], acc1);
    UNPACK2(o[4], o[5], acc2);  UNPACK2(o[6], o[7], acc3);

    float4 o0 = make_float4(o[0] * inv, o[1] * inv, o[2] * inv, o[3] * inv);
    float4 o1 = make_float4(o[4] * inv, o[5] * inv, o[6] * inv, o[7] * inv);
    float4* op = reinterpret_cast<float4*>(&out[(size_t)node * 64 + h * 8]);
    op[0] = o0;
    op[1] = o1;

    if (h == 0) g_cnt[node] = 0;   // restore invariant for next replay
}

extern "C" void kernel_launch(void* const* d_in, const int* in_sizes, int n_in,
                              void* d_out, int out_size)
{
    const float* x    = (const float*)d_in[0];
    const int*   edge = (const int*)d_in[1];
    const float* Wq   = (const float*)d_in[2];
    const float* bq   = (const float*)d_in[3];
    const float* Wk   = (const float*)d_in[4];
    const float* bk   = (const float*)d_in[5];
    const float* Wv   = (const float*)d_in[6];
    const float* bv   = (const float*)d_in[7];
    float* out = (float*)d_out;

    init_kernel<<<24, 256>>>(Wq, bq, Wk, bk, Wv, bv);
    work_kernel<<<WORK_G, 256>>>(x, edge);
    agg_kernel<<<NN / 32, 256>>>(out);   // 3125 blocks = 8 warps x 4 nodes
}